// round 10
// baseline (speedup 1.0000x reference)
#include <cuda_runtime.h>
#include <cuda_bf16.h>
#include <math.h>
#include <stdint.h>

// B=128 batches, 80 nodes (2 frames x 40), channels 256->256->128->64->2
#define NB   128
#define NN   80

#define MAXELEM (128*80*256)
__device__ float g_h1[MAXELEM];
__device__ float g_h2[MAXELEM];
__device__ float g_D [MAXELEM];
__device__ float g_T [MAXELEM];
__device__ float g_A [MAXELEM];
__device__ float g_Bf[MAXELEM];

// ---------------- mma.sync bf16 helper ----------------
__device__ __forceinline__ void mma_bf16(float* d, const uint32_t* a, const uint32_t* b) {
    asm volatile(
        "mma.sync.aligned.m16n8k16.row.col.f32.bf16.bf16.f32 "
        "{%0,%1,%2,%3}, {%4,%5,%6,%7}, {%8,%9}, {%0,%1,%2,%3};"
        : "+f"(d[0]), "+f"(d[1]), "+f"(d[2]), "+f"(d[3])
        : "r"(a[0]), "r"(a[1]), "r"(a[2]), "r"(a[3]), "r"(b[0]), "r"(b[1]));
}

#define KCH     64          // k per chunk (bf16 elems)
#define ASTRIDE 72          // smem row stride in bf16 (64 + 8 pad -> conflict-free frags)
#define TILEB   (128*ASTRIDE)
#define GEMM_SMEM (4*TILEB*2)   // 4 bf16 tiles (A hi/lo, B hi/lo) = 73728 bytes

// ---------------- Fused split-bf16 MMA GEMM ----------------
// Out[r,n] = sum_k H[hrow(r),k] * W[n, coloffW + k], fp32 via bf16 hi/lo 3-term.
// blockIdx.x decode (tilesD m-tiles for D, tilesD for T, then 39*4 A/B tiles):
//   bx < tilesD        : mode 0 (D)  hrow=r,               W block 0
//   bx < 2*tilesD      : mode 1 (T)  hrow=frame-swapped r, W block 40
//   else               : mode 2 (A/B) idx=bx-2*tilesD, l=idx/4+1, m0=(idx&3)*128
// gemm0 uses tilesD=1 (grid.x=1 -> mode 0) + bias.
// Tile: M=128, N=128 (cols beyond NOut zero-padded), K multiple of 64.
__global__ __launch_bounds__(256)
void gemm_mma(const float* __restrict__ H, const float* __restrict__ W,
              const float* __restrict__ bias,
              float* __restrict__ OutD, float* __restrict__ OutT,
              float* __restrict__ OutA, float* __restrict__ OutB,
              int NOut, int K, int ldh, int ldw, int tilesD)
{
    extern __shared__ char dsm[];
    __nv_bfloat16* sAh = (__nv_bfloat16*)dsm;
    __nv_bfloat16* sAl = sAh + TILEB;
    __nv_bfloat16* sBh = sAl + TILEB;
    __nv_bfloat16* sBl = sBh + TILEB;
    __shared__ const float* s_hrow[128];
    __shared__ const float* s_wrow[128];
    __shared__ float*       s_orow[128];

    const int tid  = threadIdx.x;
    const int lane = tid & 31;
    const int wid  = tid >> 5;
    const int gid  = lane >> 2;        // 0..7
    const int tg   = lane & 3;         // 0..3
    const int wm   = wid >> 2;         // 0..1  (M half)
    const int wn   = wid & 3;          // 0..3  (N quarter)
    const int n0   = blockIdx.y * 128;

    // decode mode / m-tile
    int bx = blockIdx.x;
    int mode, m0, l = 0, coloffW;
    if (bx < tilesD)          { mode = 0; m0 = bx * 128;            coloffW = 0; }
    else if (bx < 2 * tilesD) { mode = 1; m0 = (bx - tilesD) * 128; coloffW = 40 * K; }
    else { mode = 2; int idx = bx - 2 * tilesD; l = idx / 4 + 1; m0 = (idx & 3) * 128; coloffW = l * K; }

    // pointer tables
    if (tid < 128) {
        int gr = m0 + tid;
        int hrow, orow; float* ob;
        if (mode == 0)      { hrow = gr; ob = OutD; orow = gr; }
        else if (mode == 1) { int b = gr / 80, n = gr % 80;
                              hrow = b * 80 + ((n + 40) % 80); ob = OutT; orow = gr; }
        else { int part = gr >> 8; int bf = gr & 255; int mm = part ? l : (l - 1);
               hrow = (bf >> 1) * 80 + (bf & 1) * 40 + mm;
               ob = part ? OutB : OutA; orow = bf * 40 + mm; }
        s_hrow[tid] = H + (size_t)hrow * ldh;
        s_orow[tid] = ob + (size_t)orow * NOut;
        int bn = n0 + tid;
        s_wrow[tid] = (bn < NOut) ? (W + (size_t)bn * ldw + coloffW) : (const float*)0;
    }
    __syncthreads();

    float acc[4][4][4];
#pragma unroll
    for (int mi = 0; mi < 4; mi++)
#pragma unroll
        for (int ni = 0; ni < 4; ni++)
#pragma unroll
            for (int q = 0; q < 4; q++) acc[mi][ni][q] = 0.f;

    const int nch = K / KCH;
    for (int c = 0; c < nch; ++c) {
        const int kc = c * KCH;
        if (c) __syncthreads();        // previous chunk's compute done

        // ---- fill A (128 x 64) hi/lo ----
        for (int i = tid; i < 128 * 32; i += 256) {
            int row = i >> 5, cp = i & 31;
            float2 v = *(const float2*)(s_hrow[row] + kc + cp * 2);
            __nv_bfloat162 hp = __float22bfloat162_rn(v);
            float2 hf = __bfloat1622float2(hp);
            float2 r; r.x = v.x - hf.x; r.y = v.y - hf.y;
            __nv_bfloat162 lp = __float22bfloat162_rn(r);
            int off = row * ASTRIDE + cp * 2;
            *(__nv_bfloat162*)(sAh + off) = hp;
            *(__nv_bfloat162*)(sAl + off) = lp;
        }
        // ---- fill B (128 x 64) hi/lo (zero beyond NOut) ----
        for (int i = tid; i < 128 * 32; i += 256) {
            int row = i >> 5, cp = i & 31;
            const float* p = s_wrow[row];
            float2 v = p ? *(const float2*)(p + kc + cp * 2) : make_float2(0.f, 0.f);
            __nv_bfloat162 hp = __float22bfloat162_rn(v);
            float2 hf = __bfloat1622float2(hp);
            float2 r; r.x = v.x - hf.x; r.y = v.y - hf.y;
            __nv_bfloat162 lp = __float22bfloat162_rn(r);
            int off = row * ASTRIDE + cp * 2;
            *(__nv_bfloat162*)(sBh + off) = hp;
            *(__nv_bfloat162*)(sBl + off) = lp;
        }
        __syncthreads();

        // ---- compute: 4 x k16 steps ----
#pragma unroll
        for (int k16 = 0; k16 < 4; k16++) {
            const int kb = k16 * 16 + tg * 2;
            uint32_t bh[4][2], bl[4][2];
#pragma unroll
            for (int ni = 0; ni < 4; ni++) {
                int r = (wn * 32 + ni * 8 + gid) * ASTRIDE;
                bh[ni][0] = *(const uint32_t*)(sBh + r + kb);
                bh[ni][1] = *(const uint32_t*)(sBh + r + kb + 8);
                bl[ni][0] = *(const uint32_t*)(sBl + r + kb);
                bl[ni][1] = *(const uint32_t*)(sBl + r + kb + 8);
            }
#pragma unroll
            for (int mi = 0; mi < 4; mi++) {
                int r0 = (wm * 64 + mi * 16 + gid) * ASTRIDE;
                int r1 = r0 + 8 * ASTRIDE;
                uint32_t ah[4], al[4];
                ah[0] = *(const uint32_t*)(sAh + r0 + kb);
                ah[1] = *(const uint32_t*)(sAh + r1 + kb);
                ah[2] = *(const uint32_t*)(sAh + r0 + kb + 8);
                ah[3] = *(const uint32_t*)(sAh + r1 + kb + 8);
                al[0] = *(const uint32_t*)(sAl + r0 + kb);
                al[1] = *(const uint32_t*)(sAl + r1 + kb);
                al[2] = *(const uint32_t*)(sAl + r0 + kb + 8);
                al[3] = *(const uint32_t*)(sAl + r1 + kb + 8);
#pragma unroll
                for (int ni = 0; ni < 4; ni++) {
                    mma_bf16(acc[mi][ni], ah, bh[ni]);
                    mma_bf16(acc[mi][ni], ah, bl[ni]);
                    mma_bf16(acc[mi][ni], al, bh[ni]);
                }
            }
        }
    }

    // ---- epilogue: direct register -> global ----
#pragma unroll
    for (int mi = 0; mi < 4; mi++) {
        int lrow = wm * 64 + mi * 16 + gid;
#pragma unroll
        for (int ni = 0; ni < 4; ni++) {
            int colg = n0 + wn * 32 + ni * 8 + tg * 2;
            if (colg < NOut) {
                float b0 = bias ? bias[colg]     : 0.f;
                float b1 = bias ? bias[colg + 1] : 0.f;
                float2 v0; v0.x = acc[mi][ni][0] + b0; v0.y = acc[mi][ni][1] + b1;
                float2 v1; v1.x = acc[mi][ni][2] + b0; v1.y = acc[mi][ni][3] + b1;
                *(float2*)(s_orow[lrow]     + colg) = v0;
                *(float2*)(s_orow[lrow + 8] + colg) = v1;
            }
        }
    }
}

// ---------------- Combine: smem-staged A/B + 4-way j parallel scan ----------------
// grid (bf=256, Cout/64), block 256. out[b,f*40+j,c] = elu( bias + D + T + prefA(<j) + sufB(>j) )
__global__ void combine2_kernel(const float* __restrict__ D, const float* __restrict__ T,
                                const float* __restrict__ A, const float* __restrict__ B,
                                const float* __restrict__ bias, float* __restrict__ out,
                                int Cout)
{
    __shared__ float As[40 * 64];
    __shared__ float Bs[40 * 64];
    const int bf = blockIdx.x;
    const int c0 = blockIdx.y * 64;
    const int tid = threadIdx.x;

    for (int t = tid; t < 40 * 64; t += 256) {
        int j = t >> 6, c = t & 63;
        size_t src = (size_t)(bf * 40 + j) * Cout + c0 + c;
        As[t] = A[src];
        Bs[t] = B[src];
    }
    __syncthreads();

    const int cc = tid & 63;
    const int jg = tid >> 6;
    const int j0 = jg * 10;

    float pref = 0.f, suf = 0.f;
    for (int m = 0; m < j0; m++)      pref += As[m * 64 + cc];
    for (int m = j0 + 1; m < 40; m++) suf  += Bs[m * 64 + cc];

    const int b = bf >> 1, f = bf & 1;
    const float bias_c = bias[c0 + cc];
    const size_t rbase = (size_t)(b * 80 + f * 40) * Cout + c0 + cc;
#pragma unroll
    for (int j = j0; j < j0 + 10; j++) {
        size_t r = rbase + (size_t)j * Cout;
        float v = bias_c + D[r] + T[r] + pref + suf;
        v = (v > 0.f) ? v : expm1f(v);
        out[r] = v;
        if (j < 39) {
            pref += As[j * 64 + cc];
            suf  -= Bs[(j + 1) * 64 + cc];
        }
    }
}

// ---------------- Layer 4 direct: Cout=2, Cin=64, spiral evaluated in-kernel ----
__global__ __launch_bounds__(256)
void spiral_small_kernel(const float* __restrict__ Hin, const float* __restrict__ W4,
                         const float* __restrict__ b4, float* __restrict__ out)
{
    __shared__ float hs[80 * 64];
    __shared__ float ws[2 * 41 * 64];
    const int b = blockIdx.x;
    const int tid = threadIdx.x;
    const int wid = tid >> 5;
    const int lane = tid & 31;

    const float* hsrc = Hin + (size_t)b * 80 * 64;
    for (int t = tid; t < 80 * 64; t += 256) hs[t] = hsrc[t];
    for (int t = tid; t < 2 * 41 * 64; t += 256) ws[t] = W4[t];
    __syncthreads();

    for (int j = wid; j < 80; j += 8) {
        const int f  = (j >= 40) ? 40 : 0;
        const int jj = j - f;
        const int tnode = (j < 40) ? j + 40 : j - 40;
#pragma unroll
        for (int c = 0; c < 2; c++) {
            const float* w = ws + c * (41 * 64);
            float sum = 0.f;
            for (int idx = lane; idx < 41 * 64; idx += 32) {
                int p = idx >> 6, k = idx & 63;
                int node;
                if (p == 0)       node = j;
                else if (p <= 39) node = f + ((p - 1 < jj) ? p - 1 : p);
                else              node = tnode;
                sum += w[idx] * hs[node * 64 + k];
            }
#pragma unroll
            for (int o = 16; o > 0; o >>= 1)
                sum += __shfl_xor_sync(0xFFFFFFFFu, sum, o);
            if (lane == 0)
                out[(size_t)(b * 80 + j) * 2 + c] = sum + b4[c];
        }
    }
}

// ---------------- Host-side driver ----------------
static void run_layer(const float* h_in, const float* W, const float* bias,
                      float* h_out, int Cin, int Cout,
                      float* dD, float* dT, float* dA, float* dB)
{
    const int ldw = Cin * 41;
    const int tilesD = NB * NN / 128;                 // 80
    const int gx = 2 * tilesD + 39 * 4;               // 316
    const int ny = (Cout + 127) / 128;
    gemm_mma<<<dim3(gx, ny), 256, GEMM_SMEM>>>(h_in, W, (const float*)0,
                                               dD, dT, dA, dB,
                                               Cout, Cin, Cin, ldw, tilesD);
    combine2_kernel<<<dim3(NB * 2, Cout / 64), 256>>>(dD, dT, dA, dB, bias, h_out, Cout);
}

extern "C" void kernel_launch(void* const* d_in, const int* in_sizes, int n_in,
                              void* d_out, int out_size)
{
    const float* x  = (const float*)d_in[0];
    const float* W0 = (const float*)d_in[1];
    const float* b0 = (const float*)d_in[2];
    const float* W1 = (const float*)d_in[3];
    const float* b1 = (const float*)d_in[4];
    const float* W2 = (const float*)d_in[5];
    const float* b2 = (const float*)d_in[6];
    const float* W3 = (const float*)d_in[7];
    const float* b3 = (const float*)d_in[8];
    const float* W4 = (const float*)d_in[9];
    const float* b4 = (const float*)d_in[10];
    float* out = (float*)d_out;

    float *h1, *h2, *dD, *dT, *dA, *dB;
    cudaGetSymbolAddress((void**)&h1, g_h1);
    cudaGetSymbolAddress((void**)&h2, g_h2);
    cudaGetSymbolAddress((void**)&dD, g_D);
    cudaGetSymbolAddress((void**)&dT, g_T);
    cudaGetSymbolAddress((void**)&dA, g_A);
    cudaGetSymbolAddress((void**)&dB, g_Bf);

    cudaFuncSetAttribute(gemm_mma, cudaFuncAttributeMaxDynamicSharedMemorySize, GEMM_SMEM);

    // Initial GEMM: h1 = x @ W0^T + b0   (M=128, N=20480, K=1024), bias fused
    gemm_mma<<<dim3(1, 160), 256, GEMM_SMEM>>>(x, W0, b0, h1, h1, h1, h1,
                                               NN * 256, 1024, 1024, 1024, 1);

    // SpiralConv stack (layers 1-3 via reduced MMA GEMM + scan-combine)
    run_layer(h1, W1, b1, h2, 256, 256, dD, dT, dA, dB);   // 256 -> 256, ELU
    run_layer(h2, W2, b2, h1, 256, 128, dD, dT, dA, dB);   // 256 -> 128, ELU
    run_layer(h1, W3, b3, h2, 128,  64, dD, dT, dA, dB);   // 128 ->  64, ELU

    // Layer 4 (64 -> 2, no ELU): direct spiral evaluation
    spiral_small_kernel<<<NB, 256>>>(h2, W4, b4, out);
}

// round 11
// speedup vs baseline: 2.1463x; 2.1463x over previous
#include <cuda_runtime.h>
#include <cuda_bf16.h>
#include <math.h>
#include <stdint.h>

// B=128 batches, 80 nodes (2 frames x 40), channels 256->256->128->64->2
#define NB   128
#define NN   80

#define MAXELEM (128*80*256)
__device__ float g_D [MAXELEM];
__device__ float g_T [MAXELEM];
__device__ float g_A [MAXELEM];
__device__ float g_Bf[MAXELEM];
__device__ float g_h2[MAXELEM];          // fp32 input for final spiral layer

// bf16 hi/lo scratch
// W pack: W0 @0 (20971520), W1 @20971520 (2686976), W2 @23658496 (1343488), W3 @25001984 (335872)
#define W0OFF 0
#define W1OFF 20971520
#define W2OFF 23658496
#define W3OFF 25001984
#define WTOT  25337856
__device__ __nv_bfloat16 g_whi[WTOT], g_wlo[WTOT];
__device__ __nv_bfloat16 g_xhi[131072],  g_xlo[131072];
__device__ __nv_bfloat16 g_hahi[MAXELEM], g_halo[MAXELEM];
__device__ __nv_bfloat16 g_hbhi[MAXELEM], g_hblo[MAXELEM];

// ---------------- helpers ----------------
__device__ __forceinline__ uint32_t smem_u32(const void* p) {
    uint32_t a;
    asm("{ .reg .u64 t; cvta.to.shared.u64 t, %1; cvt.u32.u64 %0, t; }" : "=r"(a) : "l"(p));
    return a;
}
__device__ __forceinline__ void cpa16(uint32_t d, const void* s, int sz) {
    asm volatile("{ .reg .u64 g; cvta.to.global.u64 g, %1;"
                 " cp.async.ca.shared.global [%0], [g], 16, %2; }"
                 :: "r"(d), "l"(s), "r"(sz));
}
__device__ __forceinline__ void cpa_commit() {
    asm volatile("cp.async.commit_group;" ::: "memory");
}
__device__ __forceinline__ void mma_bf16(float* d, const uint32_t* a, const uint32_t* b) {
    asm volatile(
        "mma.sync.aligned.m16n8k16.row.col.f32.bf16.bf16.f32 "
        "{%0,%1,%2,%3}, {%4,%5,%6,%7}, {%8,%9}, {%0,%1,%2,%3};"
        : "+f"(d[0]), "+f"(d[1]), "+f"(d[2]), "+f"(d[3])
        : "r"(a[0]), "r"(a[1]), "r"(a[2]), "r"(a[3]), "r"(b[0]), "r"(b[1]));
}

#define KCH        64
#define TILE_BYTES 16384      // 128 rows * 128B
#define BUF_BYTES  65536      // Ah, Al, Bh, Bl
#define GEMM_SMEM  131072     // double buffered

// ---------------- fp32 -> bf16 hi/lo splitter (vectorized x4) ----------------
__global__ void conv_split(const float4* __restrict__ in,
                           __nv_bfloat162* __restrict__ hi,
                           __nv_bfloat162* __restrict__ lo, int n4)
{
    int i = blockIdx.x * blockDim.x + threadIdx.x;
    if (i >= n4) return;
    float4 v = in[i];
    float2 v0 = make_float2(v.x, v.y), v1 = make_float2(v.z, v.w);
    __nv_bfloat162 h0 = __float22bfloat162_rn(v0), h1 = __float22bfloat162_rn(v1);
    float2 f0 = __bfloat1622float2(h0), f1 = __bfloat1622float2(h1);
    float2 r0 = make_float2(v0.x - f0.x, v0.y - f0.y);
    float2 r1 = make_float2(v1.x - f1.x, v1.y - f1.y);
    hi[2*i]   = h0; hi[2*i+1] = h1;
    lo[2*i]   = __float22bfloat162_rn(r0);
    lo[2*i+1] = __float22bfloat162_rn(r1);
}

// ---------------- split-bf16 MMA GEMM, cp.async double-buffered ----------------
// Out[r,n] = sum_k H[hrow(r),k]*W[n,coloffW+k]; 3-term hi/lo bf16, fp32 acc.
// blockIdx.x decode: bx<tilesD: D (W blk 0) | bx<2*tilesD: T (frame-swap, blk 40)
//                    | else A/B: idx=bx-2*tilesD, l=idx/4+1, m0=(idx&3)*128
// gemm0: tilesD=1 (grid.x=1 -> mode 0), bias + bf16 hi/lo out fused (OHi/OLo).
// Smem tile layout: byte = row*128 + ((k>>3)^(row&7))*16 + (k&7)*2  (conflict-free)
__global__ __launch_bounds__(256)
void gemm_bf16(const __nv_bfloat16* __restrict__ Hhi, const __nv_bfloat16* __restrict__ Hlo,
               const __nv_bfloat16* __restrict__ Whi, const __nv_bfloat16* __restrict__ Wlo,
               const float* __restrict__ bias,
               float* __restrict__ OutD, float* __restrict__ OutT,
               float* __restrict__ OutA, float* __restrict__ OutB,
               __nv_bfloat16* __restrict__ OHi, __nv_bfloat16* __restrict__ OLo,
               int NOut, int K, int ldh, int ldw, int tilesD)
{
    extern __shared__ char dsm[];
    __shared__ int    s_hoff[128];
    __shared__ int    s_woff[128];
    __shared__ int    s_wok [128];
    __shared__ float* s_orow[128];
    __shared__ int    s_oidx[128];

    const int tid  = threadIdx.x;
    const int lane = tid & 31;
    const int wid  = tid >> 5;
    const int gid  = lane >> 2;
    const int tg   = lane & 3;
    const int wm   = wid >> 2;
    const int wn   = wid & 3;
    const int n0   = blockIdx.y * 128;

    int bx = blockIdx.x;
    int mode, m0, l = 0, coloffW;
    if (bx < tilesD)          { mode = 0; m0 = bx * 128;            coloffW = 0; }
    else if (bx < 2 * tilesD) { mode = 1; m0 = (bx - tilesD) * 128; coloffW = 40 * K; }
    else { mode = 2; int idx = bx - 2 * tilesD; l = idx / 4 + 1; m0 = (idx & 3) * 128; coloffW = l * K; }

    if (tid < 128) {
        int gr = m0 + tid;
        int hrow, orow; float* ob;
        if (mode == 0)      { hrow = gr; ob = OutD; orow = gr; }
        else if (mode == 1) { int b = gr / 80, n = gr % 80;
                              hrow = b * 80 + ((n + 40) % 80); ob = OutT; orow = gr; }
        else { int part = gr >> 8; int bf = gr & 255; int mm = part ? l : (l - 1);
               hrow = (bf >> 1) * 80 + (bf & 1) * 40 + mm;
               ob = part ? OutB : OutA; orow = bf * 40 + mm; }
        s_hoff[tid] = hrow * ldh;
        s_orow[tid] = ob + (size_t)orow * NOut;
        s_oidx[tid] = orow;
        int bn = n0 + tid;
        int valid = (bn < NOut);
        s_woff[tid] = valid ? (bn * ldw + coloffW) : 0;
        s_wok [tid] = valid ? 16 : 0;
    }
    __syncthreads();

    float acc[4][4][4];
#pragma unroll
    for (int mi = 0; mi < 4; mi++)
#pragma unroll
        for (int ni = 0; ni < 4; ni++)
#pragma unroll
            for (int q = 0; q < 4; q++) acc[mi][ni][q] = 0.f;

    const uint32_t dsm32 = smem_u32(dsm);
    const int nch = K / KCH;

#define FILL(BUF, KC) do {                                                     \
        uint32_t b32 = dsm32 + (BUF) * BUF_BYTES;                              \
        _Pragma("unroll")                                                      \
        for (int q = 0; q < 4; q++) {                                          \
            int s = q * 256 + tid;                                             \
            int row = s >> 3, sg = s & 7;                                      \
            uint32_t d = b32 + row * 128 + ((sg ^ (row & 7)) << 4);            \
            int ho = s_hoff[row] + (KC) + sg * 8;                              \
            cpa16(d,                  Hhi + ho, 16);                           \
            cpa16(d +     TILE_BYTES, Hlo + ho, 16);                           \
            int wo = s_woff[row] + (KC) + sg * 8;                              \
            int ok = s_wok[row];                                               \
            cpa16(d + 2 * TILE_BYTES, Whi + wo, ok);                           \
            cpa16(d + 3 * TILE_BYTES, Wlo + wo, ok);                           \
        }                                                                      \
        cpa_commit();                                                          \
    } while (0)

    FILL(0, 0);

    int buf = 0;
    for (int c = 0; c < nch; ++c) {
        const bool nx = (c + 1 < nch);
        if (nx) FILL(buf ^ 1, (c + 1) * KCH);
        if (nx) asm volatile("cp.async.wait_group 1;" ::: "memory");
        else    asm volatile("cp.async.wait_group 0;" ::: "memory");
        __syncthreads();

        const char* Ah = dsm + buf * BUF_BYTES;
        const char* Al = Ah + TILE_BYTES;
        const char* Bh = Ah + 2 * TILE_BYTES;
        const char* Bl = Ah + 3 * TILE_BYTES;
#pragma unroll
        for (int k16 = 0; k16 < 4; k16++) {
            const int sgx = ((k16 * 2) ^ gid) << 4;
            const int sgy = sgx ^ 16;
            uint32_t bh[4][2], bl[4][2];
#pragma unroll
            for (int ni = 0; ni < 4; ni++) {
                int rb = (wn * 32 + ni * 8 + gid) * 128 + tg * 4;
                bh[ni][0] = *(const uint32_t*)(Bh + rb + sgx);
                bh[ni][1] = *(const uint32_t*)(Bh + rb + sgy);
                bl[ni][0] = *(const uint32_t*)(Bl + rb + sgx);
                bl[ni][1] = *(const uint32_t*)(Bl + rb + sgy);
            }
#pragma unroll
            for (int mi = 0; mi < 4; mi++) {
                int rb0 = (wm * 64 + mi * 16 + gid) * 128 + tg * 4;
                int rb1 = rb0 + 1024;
                uint32_t ah[4], al[4];
                ah[0] = *(const uint32_t*)(Ah + rb0 + sgx);
                ah[1] = *(const uint32_t*)(Ah + rb1 + sgx);
                ah[2] = *(const uint32_t*)(Ah + rb0 + sgy);
                ah[3] = *(const uint32_t*)(Ah + rb1 + sgy);
                al[0] = *(const uint32_t*)(Al + rb0 + sgx);
                al[1] = *(const uint32_t*)(Al + rb1 + sgx);
                al[2] = *(const uint32_t*)(Al + rb0 + sgy);
                al[3] = *(const uint32_t*)(Al + rb1 + sgy);
#pragma unroll
                for (int ni = 0; ni < 4; ni++) {
                    mma_bf16(acc[mi][ni], ah, bh[ni]);
                    mma_bf16(acc[mi][ni], ah, bl[ni]);
                    mma_bf16(acc[mi][ni], al, bh[ni]);
                }
            }
        }
        __syncthreads();
        buf ^= 1;
    }

    // ---- epilogue ----
#pragma unroll
    for (int mi = 0; mi < 4; mi++) {
        int lrow = wm * 64 + mi * 16 + gid;
#pragma unroll
        for (int ni = 0; ni < 4; ni++) {
            int colg = n0 + wn * 32 + ni * 8 + tg * 2;
            if (colg < NOut) {
                float b0 = bias ? bias[colg]     : 0.f;
                float b1 = bias ? bias[colg + 1] : 0.f;
                float2 v0; v0.x = acc[mi][ni][0] + b0; v0.y = acc[mi][ni][1] + b1;
                float2 v1; v1.x = acc[mi][ni][2] + b0; v1.y = acc[mi][ni][3] + b1;
                if (OHi) {   // bf16 hi/lo out (gemm0): skip fp32 write
                    size_t o0 = (size_t)s_oidx[lrow]     * NOut + colg;
                    size_t o1 = (size_t)s_oidx[lrow + 8] * NOut + colg;
                    __nv_bfloat162 h0 = __float22bfloat162_rn(v0);
                    __nv_bfloat162 h1 = __float22bfloat162_rn(v1);
                    float2 f0 = __bfloat1622float2(h0), f1 = __bfloat1622float2(h1);
                    float2 r0 = make_float2(v0.x - f0.x, v0.y - f0.y);
                    float2 r1 = make_float2(v1.x - f1.x, v1.y - f1.y);
                    *(__nv_bfloat162*)(OHi + o0) = h0;
                    *(__nv_bfloat162*)(OHi + o1) = h1;
                    *(__nv_bfloat162*)(OLo + o0) = __float22bfloat162_rn(r0);
                    *(__nv_bfloat162*)(OLo + o1) = __float22bfloat162_rn(r1);
                } else {
                    *(float2*)(s_orow[lrow]     + colg) = v0;
                    *(float2*)(s_orow[lrow + 8] + colg) = v1;
                }
            }
        }
    }
#undef FILL
}

// ---------------- Combine: smem-staged A/B + 4-way j parallel scan ----------------
// out fp32 optional; bf16 hi/lo (next layer input) optional.
__global__ void combine2_kernel(const float* __restrict__ D, const float* __restrict__ T,
                                const float* __restrict__ A, const float* __restrict__ B,
                                const float* __restrict__ bias, float* __restrict__ out,
                                __nv_bfloat16* __restrict__ OHi, __nv_bfloat16* __restrict__ OLo,
                                int Cout)
{
    __shared__ float As[40 * 64];
    __shared__ float Bs[40 * 64];
    const int bf = blockIdx.x;
    const int c0 = blockIdx.y * 64;
    const int tid = threadIdx.x;

    for (int t = tid; t < 40 * 64; t += 256) {
        int j = t >> 6, c = t & 63;
        size_t src = (size_t)(bf * 40 + j) * Cout + c0 + c;
        As[t] = A[src];
        Bs[t] = B[src];
    }
    __syncthreads();

    const int cc = tid & 63;
    const int jg = tid >> 6;
    const int j0 = jg * 10;

    float pref = 0.f, suf = 0.f;
    for (int m = 0; m < j0; m++)      pref += As[m * 64 + cc];
    for (int m = j0 + 1; m < 40; m++) suf  += Bs[m * 64 + cc];

    const int b = bf >> 1, f = bf & 1;
    const float bias_c = bias[c0 + cc];
    const size_t rbase = (size_t)(b * 80 + f * 40) * Cout + c0 + cc;
#pragma unroll
    for (int j = j0; j < j0 + 10; j++) {
        size_t r = rbase + (size_t)j * Cout;
        float v = bias_c + D[r] + T[r] + pref + suf;
        v = (v > 0.f) ? v : expm1f(v);
        if (out) out[r] = v;
        if (OHi) {
            __nv_bfloat16 h = __float2bfloat16(v);
            OHi[r] = h;
            OLo[r] = __float2bfloat16(v - __bfloat162float(h));
        }
        if (j < 39) {
            pref += As[j * 64 + cc];
            suf  -= Bs[(j + 1) * 64 + cc];
        }
    }
}

// ---------------- Layer 4 direct: Cout=2, Cin=64, spiral evaluated in-kernel ----
__global__ __launch_bounds__(256)
void spiral_small_kernel(const float* __restrict__ Hin, const float* __restrict__ W4,
                         const float* __restrict__ b4, float* __restrict__ out)
{
    __shared__ float hs[80 * 64];
    __shared__ float ws[2 * 41 * 64];
    const int b = blockIdx.x;
    const int tid = threadIdx.x;
    const int wid = tid >> 5;
    const int lane = tid & 31;

    const float* hsrc = Hin + (size_t)b * 80 * 64;
    for (int t = tid; t < 80 * 64; t += 256) hs[t] = hsrc[t];
    for (int t = tid; t < 2 * 41 * 64; t += 256) ws[t] = W4[t];
    __syncthreads();

    for (int j = wid; j < 80; j += 8) {
        const int f  = (j >= 40) ? 40 : 0;
        const int jj = j - f;
        const int tnode = (j < 40) ? j + 40 : j - 40;
#pragma unroll
        for (int c = 0; c < 2; c++) {
            const float* w = ws + c * (41 * 64);
            float sum = 0.f;
            for (int idx = lane; idx < 41 * 64; idx += 32) {
                int p = idx >> 6, k = idx & 63;
                int node;
                if (p == 0)       node = j;
                else if (p <= 39) node = f + ((p - 1 < jj) ? p - 1 : p);
                else              node = tnode;
                sum += w[idx] * hs[node * 64 + k];
            }
#pragma unroll
            for (int o = 16; o > 0; o >>= 1)
                sum += __shfl_xor_sync(0xFFFFFFFFu, sum, o);
            if (lane == 0)
                out[(size_t)(b * 80 + j) * 2 + c] = sum + b4[c];
        }
    }
}

// ---------------- Host-side driver ----------------
static void conv(const float* src, __nv_bfloat16* hi, __nv_bfloat16* lo, int n) {
    int n4 = n / 4;
    conv_split<<<(n4 + 255) / 256, 256>>>((const float4*)src,
                                          (__nv_bfloat162*)hi, (__nv_bfloat162*)lo, n4);
}

extern "C" void kernel_launch(void* const* d_in, const int* in_sizes, int n_in,
                              void* d_out, int out_size)
{
    const float* x  = (const float*)d_in[0];
    const float* W0 = (const float*)d_in[1];
    const float* b0 = (const float*)d_in[2];
    const float* W1 = (const float*)d_in[3];
    const float* b1 = (const float*)d_in[4];
    const float* W2 = (const float*)d_in[5];
    const float* b2 = (const float*)d_in[6];
    const float* W3 = (const float*)d_in[7];
    const float* b3 = (const float*)d_in[8];
    const float* W4 = (const float*)d_in[9];
    const float* b4 = (const float*)d_in[10];
    float* out = (float*)d_out;

    float *dD, *dT, *dA, *dB, *h2;
    __nv_bfloat16 *whi, *wlo, *xhi, *xlo, *hahi, *halo, *hbhi, *hblo;
    cudaGetSymbolAddress((void**)&dD, g_D);
    cudaGetSymbolAddress((void**)&dT, g_T);
    cudaGetSymbolAddress((void**)&dA, g_A);
    cudaGetSymbolAddress((void**)&dB, g_Bf);
    cudaGetSymbolAddress((void**)&h2, g_h2);
    cudaGetSymbolAddress((void**)&whi, g_whi);
    cudaGetSymbolAddress((void**)&wlo, g_wlo);
    cudaGetSymbolAddress((void**)&xhi, g_xhi);
    cudaGetSymbolAddress((void**)&xlo, g_xlo);
    cudaGetSymbolAddress((void**)&hahi, g_hahi);
    cudaGetSymbolAddress((void**)&halo, g_halo);
    cudaGetSymbolAddress((void**)&hbhi, g_hbhi);
    cudaGetSymbolAddress((void**)&hblo, g_hblo);

    cudaFuncSetAttribute(gemm_bf16, cudaFuncAttributeMaxDynamicSharedMemorySize, GEMM_SMEM);

    // Split inputs/weights to bf16 hi/lo
    conv(x,  xhi, xlo, 128 * 1024);
    conv(W0, whi + W0OFF, wlo + W0OFF, 20480 * 1024);
    conv(W1, whi + W1OFF, wlo + W1OFF, 256 * 10496);
    conv(W2, whi + W2OFF, wlo + W2OFF, 128 * 10496);
    conv(W3, whi + W3OFF, wlo + W3OFF, 64 * 5248);

    const int tilesD = NB * NN / 128;            // 80
    const int gx = 2 * tilesD + 39 * 4;          // 316

    // gemm0: h1(bf16 hi/lo) = x @ W0^T + b0  (M=128, N=20480, K=1024)
    gemm_bf16<<<dim3(1, 160), 256, GEMM_SMEM>>>(
        xhi, xlo, whi + W0OFF, wlo + W0OFF, b0,
        dD, dD, dD, dD, hahi, halo, NN * 256, 1024, 1024, 1024, 1);

    // Layer 1: 256->256, ELU  (in: ha, out: hb)
    gemm_bf16<<<dim3(gx, 2), 256, GEMM_SMEM>>>(
        hahi, halo, whi + W1OFF, wlo + W1OFF, (const float*)0,
        dD, dT, dA, dB, (__nv_bfloat16*)0, (__nv_bfloat16*)0, 256, 256, 256, 10496, tilesD);
    combine2_kernel<<<dim3(NB * 2, 4), 256>>>(dD, dT, dA, dB, b1,
        (float*)0, hbhi, hblo, 256);

    // Layer 2: 256->128, ELU  (in: hb, out: ha)
    gemm_bf16<<<dim3(gx, 1), 256, GEMM_SMEM>>>(
        hbhi, hblo, whi + W2OFF, wlo + W2OFF, (const float*)0,
        dD, dT, dA, dB, (__nv_bfloat16*)0, (__nv_bfloat16*)0, 128, 256, 256, 10496, tilesD);
    combine2_kernel<<<dim3(NB * 2, 2), 256>>>(dD, dT, dA, dB, b2,
        (float*)0, hahi, halo, 128);

    // Layer 3: 128->64, ELU  (in: ha, out: h2 fp32 for spiral)
    gemm_bf16<<<dim3(gx, 1), 256, GEMM_SMEM>>>(
        hahi, halo, whi + W3OFF, wlo + W3OFF, (const float*)0,
        dD, dT, dA, dB, (__nv_bfloat16*)0, (__nv_bfloat16*)0, 64, 128, 128, 5248, tilesD);
    combine2_kernel<<<dim3(NB * 2, 1), 256>>>(dD, dT, dA, dB, b3,
        h2, (__nv_bfloat16*)0, (__nv_bfloat16*)0, 64);

    // Layer 4 (64 -> 2, no ELU): direct spiral evaluation
    spiral_small_kernel<<<NB, 256>>>(h2, W4, b4, out);
}

// round 14
// speedup vs baseline: 2.2345x; 1.0411x over previous
#include <cuda_runtime.h>
#include <cuda_bf16.h>
#include <math.h>
#include <stdint.h>

// B=128 batches, 80 nodes (2 frames x 40), channels 256->256->128->64->2
#define NB   128
#define NN   80

#define MAXELEM (128*80*256)
__device__ float g_D [MAXELEM];
__device__ float g_T [MAXELEM];
__device__ float g_A [MAXELEM];
__device__ float g_Bf[MAXELEM];
__device__ float g_h2[MAXELEM];          // fp32 input for final spiral layer

// bf16 hi/lo scratch
// W pack: W0 @0 (20971520), W1 @20971520 (2686976), W2 @23658496 (1343488), W3 @25001984 (335872)
#define W0OFF 0
#define W1OFF 20971520
#define W2OFF 23658496
#define W3OFF 25001984
#define WTOT  25337856
__device__ __nv_bfloat16 g_whi[WTOT], g_wlo[WTOT];
__device__ __nv_bfloat16 g_xhi[131072],  g_xlo[131072];
__device__ __nv_bfloat16 g_hahi[MAXELEM], g_halo[MAXELEM];
__device__ __nv_bfloat16 g_hbhi[MAXELEM], g_hblo[MAXELEM];

// ---------------- helpers ----------------
__device__ __forceinline__ uint32_t smem_u32(const void* p) {
    uint32_t a;
    asm("{ .reg .u64 t; cvta.to.shared.u64 t, %1; cvt.u32.u64 %0, t; }" : "=r"(a) : "l"(p));
    return a;
}
__device__ __forceinline__ void cpa16(uint32_t d, const void* s, int sz) {
    asm volatile("{ .reg .u64 g; cvta.to.global.u64 g, %1;"
                 " cp.async.ca.shared.global [%0], [g], 16, %2; }"
                 :: "r"(d), "l"(s), "r"(sz));
}
__device__ __forceinline__ void cpa_commit() {
    asm volatile("cp.async.commit_group;" ::: "memory");
}
__device__ __forceinline__ void mma_bf16(float* d, const uint32_t* a, const uint32_t* b) {
    asm volatile(
        "mma.sync.aligned.m16n8k16.row.col.f32.bf16.bf16.f32 "
        "{%0,%1,%2,%3}, {%4,%5,%6,%7}, {%8,%9}, {%0,%1,%2,%3};"
        : "+f"(d[0]), "+f"(d[1]), "+f"(d[2]), "+f"(d[3])
        : "r"(a[0]), "r"(a[1]), "r"(a[2]), "r"(a[3]), "r"(b[0]), "r"(b[1]));
}

#define KCH        64
#define TILE_A     8192       // 64 rows * 128B
#define TILE_B     16384      // 128 rows * 128B
#define BUF_BYTES  49152      // Ah, Al, Bh, Bl
#define GEMM_SMEM  98304      // double buffered -> 2 CTAs/SM

// ---------------- fused fp32 -> bf16 hi/lo splitter (x, W0..W3 in one launch) --
// 8 elems per thread, 16B hi/lo stores.
#define CX0 16384
#define CX1 (CX0 + 2621440)
#define CX2 (CX1 + 335872)
#define CX3 (CX2 + 167936)
#define CXT (CX3 + 41984)
__global__ void conv_all(const float4* __restrict__ x,  const float4* __restrict__ W0,
                         const float4* __restrict__ W1, const float4* __restrict__ W2,
                         const float4* __restrict__ W3)
{
    int i = blockIdx.x * blockDim.x + threadIdx.x;
    if (i >= CXT) return;
    const float4* src; __nv_bfloat16 *hp, *lp; int idx;
    if (i < CX0)      { src = x;  idx = i;       hp = g_xhi;         lp = g_xlo; }
    else if (i < CX1) { src = W0; idx = i - CX0; hp = g_whi + W0OFF; lp = g_wlo + W0OFF; }
    else if (i < CX2) { src = W1; idx = i - CX1; hp = g_whi + W1OFF; lp = g_wlo + W1OFF; }
    else if (i < CX3) { src = W2; idx = i - CX2; hp = g_whi + W2OFF; lp = g_wlo + W2OFF; }
    else              { src = W3; idx = i - CX3; hp = g_whi + W3OFF; lp = g_wlo + W3OFF; }

    float4 a = src[idx * 2], b = src[idx * 2 + 1];
    float2 v[4] = { {a.x, a.y}, {a.z, a.w}, {b.x, b.y}, {b.z, b.w} };
    __nv_bfloat162 hv[4], lv[4];
#pragma unroll
    for (int q = 0; q < 4; q++) {
        hv[q] = __float22bfloat162_rn(v[q]);
        float2 f = __bfloat1622float2(hv[q]);
        float2 r = make_float2(v[q].x - f.x, v[q].y - f.y);
        lv[q] = __float22bfloat162_rn(r);
    }
    *(uint4*)(hp + idx * 8) = *(uint4*)hv;
    *(uint4*)(lp + idx * 8) = *(uint4*)lv;
}

// ---------------- split-bf16 MMA GEMM, M-tile 64, cp.async double-buffered ------
// Out[r,n] = sum_k H[hrow(r),k]*W[n,coloffW+k]; 3-term hi/lo bf16, fp32 acc.
// blockIdx.x decode (64-row m-tiles):
//   bx < tilesD        : D  (W blk 0)     hrow = r
//   bx < 2*tilesD      : T  (frame-swap)  W blk 40
//   else               : A/B: idx=bx-2*tilesD, l=idx/8+1, m0=(idx&7)*64
// gemm0: grid.x=2, tilesD=2 -> mode 0 only; bias + bf16 hi/lo out fused.
// Smem tile layout: byte = row*128 + ((seg ^ (row&7))*16) + (k&7)*2  (conflict-free)
__global__ __launch_bounds__(256, 2)
void gemm_bf16(const __nv_bfloat16* __restrict__ Hhi, const __nv_bfloat16* __restrict__ Hlo,
               const __nv_bfloat16* __restrict__ Whi, const __nv_bfloat16* __restrict__ Wlo,
               const float* __restrict__ bias,
               float* __restrict__ OutD, float* __restrict__ OutT,
               float* __restrict__ OutA, float* __restrict__ OutB,
               __nv_bfloat16* __restrict__ OHi, __nv_bfloat16* __restrict__ OLo,
               int NOut, int K, int ldh, int ldw, int tilesD)
{
    extern __shared__ char dsm[];
    __shared__ int    s_hoff[64];
    __shared__ float* s_orow[64];
    __shared__ int    s_oidx[64];
    __shared__ int    s_woff[128];
    __shared__ int    s_wok [128];

    const int tid  = threadIdx.x;
    const int lane = tid & 31;
    const int wid  = tid >> 5;
    const int gid  = lane >> 2;
    const int tg   = lane & 3;
    const int wm   = wid >> 2;        // 0..1 -> 32-row half
    const int wn   = wid & 3;         // 0..3 -> 32-col quarter
    const int n0   = blockIdx.y * 128;

    int bx = blockIdx.x;
    int mode, m0, l = 0, coloffW;
    if (bx < tilesD)          { mode = 0; m0 = bx * 64;             coloffW = 0; }
    else if (bx < 2 * tilesD) { mode = 1; m0 = (bx - tilesD) * 64;  coloffW = 40 * K; }
    else { mode = 2; int idx = bx - 2 * tilesD; l = idx >> 3; m0 = (idx & 7) * 64; l += 1; coloffW = l * K; }

    if (tid < 64) {
        int gr = m0 + tid;
        int hrow, orow; float* ob;
        if (mode == 0)      { hrow = gr; ob = OutD; orow = gr; }
        else if (mode == 1) { int b = gr / 80, n = gr % 80;
                              hrow = b * 80 + ((n + 40) % 80); ob = OutT; orow = gr; }
        else { int part = gr >> 8; int bf = gr & 255; int mm = part ? l : (l - 1);
               hrow = (bf >> 1) * 80 + (bf & 1) * 40 + mm;
               ob = part ? OutB : OutA; orow = bf * 40 + mm; }
        s_hoff[tid] = hrow * ldh;
        s_orow[tid] = ob + (size_t)orow * NOut;
        s_oidx[tid] = orow;
    }
    if (tid < 128) {
        int bn = n0 + tid;
        int valid = (bn < NOut);
        s_woff[tid] = valid ? (bn * ldw + coloffW) : 0;
        s_wok [tid] = valid ? 16 : 0;
    }
    __syncthreads();

    float acc[2][4][4];
#pragma unroll
    for (int mi = 0; mi < 2; mi++)
#pragma unroll
        for (int ni = 0; ni < 4; ni++)
#pragma unroll
            for (int q = 0; q < 4; q++) acc[mi][ni][q] = 0.f;

    const uint32_t dsm32 = smem_u32(dsm);
    const int nch = K / KCH;

#define FILL(BUF, KC) do {                                                     \
        uint32_t b32 = dsm32 + (BUF) * BUF_BYTES;                              \
        _Pragma("unroll")                                                      \
        for (int q = 0; q < 2; q++) {                                          \
            int s = q * 256 + tid;                                             \
            int row = s >> 3, sg = s & 7;                                      \
            uint32_t d = b32 + row * 128 + ((sg ^ (row & 7)) << 4);            \
            int ho = s_hoff[row] + (KC) + sg * 8;                              \
            cpa16(d,          Hhi + ho, 16);                                   \
            cpa16(d + TILE_A, Hlo + ho, 16);                                   \
        }                                                                      \
        _Pragma("unroll")                                                      \
        for (int q = 0; q < 4; q++) {                                          \
            int s = q * 256 + tid;                                             \
            int row = s >> 3, sg = s & 7;                                      \
            uint32_t d = b32 + 2 * TILE_A + row * 128 + ((sg ^ (row & 7)) << 4); \
            int wo = s_woff[row] + (KC) + sg * 8;                              \
            int ok = s_wok[row];                                               \
            cpa16(d,          Whi + wo, ok);                                   \
            cpa16(d + TILE_B, Wlo + wo, ok);                                   \
        }                                                                      \
        cpa_commit();                                                          \
    } while (0)

    FILL(0, 0);

    int buf = 0;
    for (int c = 0; c < nch; ++c) {
        const bool nx = (c + 1 < nch);
        if (nx) FILL(buf ^ 1, (c + 1) * KCH);
        if (nx) asm volatile("cp.async.wait_group 1;" ::: "memory");
        else    asm volatile("cp.async.wait_group 0;" ::: "memory");
        __syncthreads();

        const char* Ah = dsm + buf * BUF_BYTES;
        const char* Al = Ah + TILE_A;
        const char* Bh = Ah + 2 * TILE_A;
        const char* Bl = Bh + TILE_B;
#pragma unroll
        for (int k16 = 0; k16 < 4; k16++) {
            const int sgx = ((k16 * 2) ^ gid) << 4;
            const int sgy = sgx ^ 16;
            uint32_t bh[4][2], bl[4][2];
#pragma unroll
            for (int ni = 0; ni < 4; ni++) {
                int rb = (wn * 32 + ni * 8 + gid) * 128 + tg * 4;
                bh[ni][0] = *(const uint32_t*)(Bh + rb + sgx);
                bh[ni][1] = *(const uint32_t*)(Bh + rb + sgy);
                bl[ni][0] = *(const uint32_t*)(Bl + rb + sgx);
                bl[ni][1] = *(const uint32_t*)(Bl + rb + sgy);
            }
#pragma unroll
            for (int mi = 0; mi < 2; mi++) {
                int rb0 = (wm * 32 + mi * 16 + gid) * 128 + tg * 4;
                int rb1 = rb0 + 1024;
                uint32_t ah[4], al[4];
                ah[0] = *(const uint32_t*)(Ah + rb0 + sgx);
                ah[1] = *(const uint32_t*)(Ah + rb1 + sgx);
                ah[2] = *(const uint32_t*)(Ah + rb0 + sgy);
                ah[3] = *(const uint32_t*)(Ah + rb1 + sgy);
                al[0] = *(const uint32_t*)(Al + rb0 + sgx);
                al[1] = *(const uint32_t*)(Al + rb1 + sgx);
                al[2] = *(const uint32_t*)(Al + rb0 + sgy);
                al[3] = *(const uint32_t*)(Al + rb1 + sgy);
#pragma unroll
                for (int ni = 0; ni < 4; ni++) {
                    mma_bf16(acc[mi][ni], ah, bh[ni]);
                    mma_bf16(acc[mi][ni], ah, bl[ni]);
                    mma_bf16(acc[mi][ni], al, bh[ni]);
                }
            }
        }
        __syncthreads();
        buf ^= 1;
    }

    // ---- epilogue ----
#pragma unroll
    for (int mi = 0; mi < 2; mi++) {
        int lrow = wm * 32 + mi * 16 + gid;
#pragma unroll
        for (int ni = 0; ni < 4; ni++) {
            int colg = n0 + wn * 32 + ni * 8 + tg * 2;
            if (colg < NOut) {
                float b0 = bias ? bias[colg]     : 0.f;
                float b1 = bias ? bias[colg + 1] : 0.f;
                float2 v0; v0.x = acc[mi][ni][0] + b0; v0.y = acc[mi][ni][1] + b1;
                float2 v1; v1.x = acc[mi][ni][2] + b0; v1.y = acc[mi][ni][3] + b1;
                if (OHi) {   // bf16 hi/lo out (gemm0): skip fp32 write
                    size_t o0 = (size_t)s_oidx[lrow]     * NOut + colg;
                    size_t o1 = (size_t)s_oidx[lrow + 8] * NOut + colg;
                    __nv_bfloat162 h0 = __float22bfloat162_rn(v0);
                    __nv_bfloat162 h1 = __float22bfloat162_rn(v1);
                    float2 f0 = __bfloat1622float2(h0), f1 = __bfloat1622float2(h1);
                    float2 r0 = make_float2(v0.x - f0.x, v0.y - f0.y);
                    float2 r1 = make_float2(v1.x - f1.x, v1.y - f1.y);
                    *(__nv_bfloat162*)(OHi + o0) = h0;
                    *(__nv_bfloat162*)(OHi + o1) = h1;
                    *(__nv_bfloat162*)(OLo + o0) = __float22bfloat162_rn(r0);
                    *(__nv_bfloat162*)(OLo + o1) = __float22bfloat162_rn(r1);
                } else {
                    *(float2*)(s_orow[lrow]     + colg) = v0;
                    *(float2*)(s_orow[lrow + 8] + colg) = v1;
                }
            }
        }
    }
#undef FILL
}

// ---------------- Combine: smem-staged A/B + 4-way j parallel scan ----------------
__global__ void combine2_kernel(const float* __restrict__ D, const float* __restrict__ T,
                                const float* __restrict__ A, const float* __restrict__ B,
                                const float* __restrict__ bias, float* __restrict__ out,
                                __nv_bfloat16* __restrict__ OHi, __nv_bfloat16* __restrict__ OLo,
                                int Cout)
{
    __shared__ float As[40 * 64];
    __shared__ float Bs[40 * 64];
    const int bf = blockIdx.x;
    const int c0 = blockIdx.y * 64;
    const int tid = threadIdx.x;

    for (int t = tid; t < 40 * 64; t += 256) {
        int j = t >> 6, c = t & 63;
        size_t src = (size_t)(bf * 40 + j) * Cout + c0 + c;
        As[t] = A[src];
        Bs[t] = B[src];
    }
    __syncthreads();

    const int cc = tid & 63;
    const int jg = tid >> 6;
    const int j0 = jg * 10;

    float pref = 0.f, suf = 0.f;
    for (int m = 0; m < j0; m++)      pref += As[m * 64 + cc];
    for (int m = j0 + 1; m < 40; m++) suf  += Bs[m * 64 + cc];

    const int b = bf >> 1, f = bf & 1;
    const float bias_c = bias[c0 + cc];
    const size_t rbase = (size_t)(b * 80 + f * 40) * Cout + c0 + cc;
#pragma unroll
    for (int j = j0; j < j0 + 10; j++) {
        size_t r = rbase + (size_t)j * Cout;
        float v = bias_c + D[r] + T[r] + pref + suf;
        v = (v > 0.f) ? v : expm1f(v);
        if (out) out[r] = v;
        if (OHi) {
            __nv_bfloat16 h = __float2bfloat16(v);
            OHi[r] = h;
            OLo[r] = __float2bfloat16(v - __bfloat162float(h));
        }
        if (j < 39) {
            pref += As[j * 64 + cc];
            suf  -= Bs[(j + 1) * 64 + cc];
        }
    }
}

// ---------------- Layer 4 direct: Cout=2, Cin=64, spiral evaluated in-kernel ----
__global__ __launch_bounds__(256)
void spiral_small_kernel(const float* __restrict__ Hin, const float* __restrict__ W4,
                         const float* __restrict__ b4, float* __restrict__ out)
{
    __shared__ float hs[80 * 64];
    __shared__ float ws[2 * 41 * 64];
    const int b = blockIdx.x;
    const int tid = threadIdx.x;
    const int wid = tid >> 5;
    const int lane = tid & 31;

    const float* hsrc = Hin + (size_t)b * 80 * 64;
    for (int t = tid; t < 80 * 64; t += 256) hs[t] = hsrc[t];
    for (int t = tid; t < 2 * 41 * 64; t += 256) ws[t] = W4[t];
    __syncthreads();

    for (int j = wid; j < 80; j += 8) {
        const int f  = (j >= 40) ? 40 : 0;
        const int jj = j - f;
        const int tnode = (j < 40) ? j + 40 : j - 40;
#pragma unroll
        for (int c = 0; c < 2; c++) {
            const float* w = ws + c * (41 * 64);
            float sum = 0.f;
            for (int idx = lane; idx < 41 * 64; idx += 32) {
                int p = idx >> 6, k = idx & 63;
                int node;
                if (p == 0)       node = j;
                else if (p <= 39) node = f + ((p - 1 < jj) ? p - 1 : p);
                else              node = tnode;
                sum += w[idx] * hs[node * 64 + k];
            }
#pragma unroll
            for (int o = 16; o > 0; o >>= 1)
                sum += __shfl_xor_sync(0xFFFFFFFFu, sum, o);
            if (lane == 0)
                out[(size_t)(b * 80 + j) * 2 + c] = sum + b4[c];
        }
    }
}

// ---------------- Host-side driver ----------------
extern "C" void kernel_launch(void* const* d_in, const int* in_sizes, int n_in,
                              void* d_out, int out_size)
{
    const float* x  = (const float*)d_in[0];
    const float* W0 = (const float*)d_in[1];
    const float* b0 = (const float*)d_in[2];
    const float* W1 = (const float*)d_in[3];
    const float* b1 = (const float*)d_in[4];
    const float* W2 = (const float*)d_in[5];
    const float* b2 = (const float*)d_in[6];
    const float* W3 = (const float*)d_in[7];
    const float* b3 = (const float*)d_in[8];
    const float* W4 = (const float*)d_in[9];
    const float* b4 = (const float*)d_in[10];
    float* out = (float*)d_out;

    float *dD, *dT, *dA, *dB, *h2;
    __nv_bfloat16 *whi, *wlo, *xhi, *xlo, *hahi, *halo, *hbhi, *hblo;
    cudaGetSymbolAddress((void**)&dD, g_D);
    cudaGetSymbolAddress((void**)&dT, g_T);
    cudaGetSymbolAddress((void**)&dA, g_A);
    cudaGetSymbolAddress((void**)&dB, g_Bf);
    cudaGetSymbolAddress((void**)&h2, g_h2);
    cudaGetSymbolAddress((void**)&whi, g_whi);
    cudaGetSymbolAddress((void**)&wlo, g_wlo);
    cudaGetSymbolAddress((void**)&xhi, g_xhi);
    cudaGetSymbolAddress((void**)&xlo, g_xlo);
    cudaGetSymbolAddress((void**)&hahi, g_hahi);
    cudaGetSymbolAddress((void**)&halo, g_halo);
    cudaGetSymbolAddress((void**)&hbhi, g_hbhi);
    cudaGetSymbolAddress((void**)&hblo, g_hblo);

    cudaFuncSetAttribute(gemm_bf16, cudaFuncAttributeMaxDynamicSharedMemorySize, GEMM_SMEM);

    // Split x + all W to bf16 hi/lo (one launch)
    conv_all<<<(CXT + 255) / 256, 256>>>((const float4*)x, (const float4*)W0,
                                         (const float4*)W1, (const float4*)W2,
                                         (const float4*)W3);

    const int tilesD = NB * NN / 64;             // 160 (64-row tiles)
    const int gx = 2 * tilesD + 39 * 8;          // 632

    // gemm0: h1(bf16 hi/lo) = x @ W0^T + b0  (M=128 -> 2 m-tiles, N=20480, K=1024)
    gemm_bf16<<<dim3(2, 160), 256, GEMM_SMEM>>>(
        xhi, xlo, whi + W0OFF, wlo + W0OFF, b0,
        dD, dD, dD, dD, hahi, halo, NN * 256, 1024, 1024, 1024, 2);

    // Layer 1: 256->256, ELU  (in: ha, out: hb)
    gemm_bf16<<<dim3(gx, 2), 256, GEMM_SMEM>>>(
        hahi, halo, whi + W1OFF, wlo + W1OFF, (const float*)0,
        dD, dT, dA, dB, (__nv_bfloat16*)0, (__nv_bfloat16*)0, 256, 256, 256, 10496, tilesD);
    combine2_kernel<<<dim3(NB * 2, 4), 256>>>(dD, dT, dA, dB, b1,
        (float*)0, hbhi, hblo, 256);

    // Layer 2: 256->128, ELU  (in: hb, out: ha)
    gemm_bf16<<<dim3(gx, 1), 256, GEMM_SMEM>>>(
        hbhi, hblo, whi + W2OFF, wlo + W2OFF, (const float*)0,
        dD, dT, dA, dB, (__nv_bfloat16*)0, (__nv_bfloat16*)0, 128, 256, 256, 10496, tilesD);
    combine2_kernel<<<dim3(NB * 2, 2), 256>>>(dD, dT, dA, dB, b2,
        (float*)0, hahi, halo, 128);

    // Layer 3: 128->64, ELU  (in: ha, out: h2 fp32 for spiral)
    gemm_bf16<<<dim3(gx, 1), 256, GEMM_SMEM>>>(
        hahi, halo, whi + W3OFF, wlo + W3OFF, (const float*)0,
        dD, dT, dA, dB, (__nv_bfloat16*)0, (__nv_bfloat16*)0, 64, 128, 128, 5248, tilesD);
    combine2_kernel<<<dim3(NB * 2, 1), 256>>>(dD, dT, dA, dB, b3,
        h2, (__nv_bfloat16*)0, (__nv_bfloat16*)0, 64);

    // Layer 4 (64 -> 2, no ELU): direct spiral evaluation
    spiral_small_kernel<<<NB, 256>>>(h2, W4, b4, out);
}

// round 17
// speedup vs baseline: 2.4395x; 1.0917x over previous
#include <cuda_runtime.h>
#include <cuda_bf16.h>
#include <math.h>
#include <stdint.h>

// B=128 batches, 80 nodes (2 frames x 40), channels 256->256->128->64->2
#define NB   128
#define NN   80

#define MAXELEM (128*80*256)
__device__ float g_D [MAXELEM];
__device__ float g_A [MAXELEM];
__device__ float g_Bf[MAXELEM];
__device__ float g_h2[MAXELEM];          // fp32 input for final spiral layer

// bf16 hi/lo scratch (W1..W3 + x + activations; W0 streamed fp32 in gemm0)
#define W1OFF 0
#define W2OFF 2686976
#define W3OFF 4030464
#define WTOT  4366336
__device__ __nv_bfloat16 g_whi[WTOT], g_wlo[WTOT];
__device__ __nv_bfloat16 g_xhi[131072],  g_xlo[131072];
__device__ __nv_bfloat16 g_hahi[MAXELEM], g_halo[MAXELEM];
__device__ __nv_bfloat16 g_hbhi[MAXELEM], g_hblo[MAXELEM];

// ---------------- helpers ----------------
__device__ __forceinline__ uint32_t smem_u32(const void* p) {
    uint32_t a;
    asm("{ .reg .u64 t; cvta.to.shared.u64 t, %1; cvt.u32.u64 %0, t; }" : "=r"(a) : "l"(p));
    return a;
}
__device__ __forceinline__ void cpa16(uint32_t d, const void* s, int sz) {
    asm volatile("{ .reg .u64 g; cvta.to.global.u64 g, %1;"
                 " cp.async.ca.shared.global [%0], [g], 16, %2; }"
                 :: "r"(d), "l"(s), "r"(sz));
}
__device__ __forceinline__ void cpa_commit() {
    asm volatile("cp.async.commit_group;" ::: "memory");
}
__device__ __forceinline__ void mma_bf16(float* d, const uint32_t* a, const uint32_t* b) {
    asm volatile(
        "mma.sync.aligned.m16n8k16.row.col.f32.bf16.bf16.f32 "
        "{%0,%1,%2,%3}, {%4,%5,%6,%7}, {%8,%9}, {%0,%1,%2,%3};"
        : "+f"(d[0]), "+f"(d[1]), "+f"(d[2]), "+f"(d[3])
        : "r"(a[0]), "r"(a[1]), "r"(a[2]), "r"(a[3]), "r"(b[0]), "r"(b[1]));
}

#define KCH        64
#define TILE_A     8192       // 64 rows * 128B
#define TILE_B     16384      // 128 rows * 128B
#define BUF_BYTES  49152      // Ah, Al, Bh, Bl
#define GEMM_SMEM  98304      // double buffered -> 2 CTAs/SM

// ---------------- fused fp32 -> bf16 hi/lo splitter (x, W1..W3) ----------------
#define CX0 16384
#define CX1 (CX0 + 335872)
#define CX2 (CX1 + 167936)
#define CXT (CX2 + 41984)
__global__ void conv_all(const float4* __restrict__ x,  const float4* __restrict__ W1,
                         const float4* __restrict__ W2, const float4* __restrict__ W3)
{
    int i = blockIdx.x * blockDim.x + threadIdx.x;
    if (i >= CXT) return;
    const float4* src; __nv_bfloat16 *hp, *lp; int idx;
    if (i < CX0)      { src = x;  idx = i;       hp = g_xhi;         lp = g_xlo; }
    else if (i < CX1) { src = W1; idx = i - CX0; hp = g_whi + W1OFF; lp = g_wlo + W1OFF; }
    else if (i < CX2) { src = W2; idx = i - CX1; hp = g_whi + W2OFF; lp = g_wlo + W2OFF; }
    else              { src = W3; idx = i - CX2; hp = g_whi + W3OFF; lp = g_wlo + W3OFF; }

    float4 a = src[idx * 2], b = src[idx * 2 + 1];
    float2 v[4] = { {a.x, a.y}, {a.z, a.w}, {b.x, b.y}, {b.z, b.w} };
    __nv_bfloat162 hv[4], lv[4];
#pragma unroll
    for (int q = 0; q < 4; q++) {
        hv[q] = __float22bfloat162_rn(v[q]);
        float2 f = __bfloat1622float2(hv[q]);
        float2 r = make_float2(v[q].x - f.x, v[q].y - f.y);
        lv[q] = __float22bfloat162_rn(r);
    }
    *(uint4*)(hp + idx * 8) = *(uint4*)hv;
    *(uint4*)(lp + idx * 8) = *(uint4*)lv;
}

// ---------------- gemm0: x @ W0^T + b0, W0 streamed fp32, converted in-kernel ---
// M=128 (one m-tile), N tile 128 (grid.y=160), K=1024 in 16 chunks of 64.
// A (x) pre-split bf16 hi/lo via cp.async; W fp32 LDG->regs->convert->STS bf16.
// Output: bf16 hi/lo (h1 for layer 1) with bias fused; no fp32 write.
#define G0_BUF  65536     // Ah 16K, Al 16K, Wh 16K, Wl 16K
#define G0_SMEM 131072
__global__ __launch_bounds__(256, 1)
void gemm0_kernel(const __nv_bfloat16* __restrict__ xhi, const __nv_bfloat16* __restrict__ xlo,
                  const float* __restrict__ W, const float* __restrict__ bias,
                  __nv_bfloat16* __restrict__ OHi, __nv_bfloat16* __restrict__ OLo)
{
    extern __shared__ char dsm[];
    const int tid  = threadIdx.x;
    const int lane = tid & 31;
    const int wid  = tid >> 5;
    const int gid  = lane >> 2;
    const int tg   = lane & 3;
    const int wm   = wid >> 2;       // 0..1 (64-row half of 128-row A)
    const int wn   = wid & 3;        // 0..3 (32-col quarter)
    const int n0   = blockIdx.y * 128;
    const uint32_t dsm32 = smem_u32(dsm);

    float4 wreg[8];

#define AFILL(BUF, KC) do {                                                    \
        uint32_t b32 = dsm32 + (BUF) * G0_BUF;                                 \
        _Pragma("unroll")                                                      \
        for (int q = 0; q < 4; q++) {                                          \
            int s = q * 256 + tid; int row = s >> 3, sg = s & 7;               \
            uint32_t d = b32 + row * 128 + ((sg ^ (row & 7)) << 4);            \
            int ho = row * 1024 + (KC) + sg * 8;                               \
            cpa16(d,         xhi + ho, 16);                                    \
            cpa16(d + 16384, xlo + ho, 16);                                    \
        }                                                                      \
        cpa_commit();                                                          \
    } while (0)

#define WLDG(KC) do {                                                          \
        _Pragma("unroll")                                                      \
        for (int q = 0; q < 8; q++) {                                          \
            int f = q * 256 + tid; int row = f >> 4, k4 = (f & 15) * 4;        \
            wreg[q] = *(const float4*)(W + (size_t)(n0 + row) * 1024 + (KC) + k4); \
        }                                                                      \
    } while (0)

#define WSTS(BUF) do {                                                         \
        _Pragma("unroll")                                                      \
        for (int q = 0; q < 8; q++) {                                          \
            int f = q * 256 + tid; int row = f >> 4, k4 = (f & 15) * 4;        \
            uint32_t byte = row * 128 + (((k4 >> 3) ^ (row & 7)) << 4) + ((k4 & 7) << 1); \
            float2 p0 = make_float2(wreg[q].x, wreg[q].y);                     \
            float2 p1 = make_float2(wreg[q].z, wreg[q].w);                     \
            __nv_bfloat162 h0 = __float22bfloat162_rn(p0);                     \
            __nv_bfloat162 h1 = __float22bfloat162_rn(p1);                     \
            float2 f0 = __bfloat1622float2(h0), f1 = __bfloat1622float2(h1);   \
            __nv_bfloat162 l0 = __float22bfloat162_rn(make_float2(p0.x - f0.x, p0.y - f0.y)); \
            __nv_bfloat162 l1 = __float22bfloat162_rn(make_float2(p1.x - f1.x, p1.y - f1.y)); \
            uint2 hv, lv;                                                      \
            hv.x = *(uint32_t*)&h0; hv.y = *(uint32_t*)&h1;                    \
            lv.x = *(uint32_t*)&l0; lv.y = *(uint32_t*)&l1;                    \
            *(uint2*)(dsm + (BUF) * G0_BUF + 32768 + byte) = hv;               \
            *(uint2*)(dsm + (BUF) * G0_BUF + 49152 + byte) = lv;               \
        }                                                                      \
    } while (0)

    float acc[4][4][4];
#pragma unroll
    for (int mi = 0; mi < 4; mi++)
#pragma unroll
        for (int ni = 0; ni < 4; ni++)
#pragma unroll
            for (int q = 0; q < 4; q++) acc[mi][ni][q] = 0.f;

    WLDG(0);
    AFILL(0, 0);
    WSTS(0);

    int buf = 0;
    for (int c = 0; c < 16; ++c) {
        const bool nx = (c < 15);
        if (nx) { WLDG((c + 1) * 64); AFILL(buf ^ 1, (c + 1) * 64); }
        if (nx) asm volatile("cp.async.wait_group 1;" ::: "memory");
        else    asm volatile("cp.async.wait_group 0;" ::: "memory");
        __syncthreads();

        const char* Ah = dsm + buf * G0_BUF;
        const char* Al = Ah + 16384;
        const char* Bh = Ah + 32768;
        const char* Bl = Ah + 49152;
#pragma unroll
        for (int k16 = 0; k16 < 4; k16++) {
            const int sgx = ((k16 * 2) ^ gid) << 4;
            const int sgy = sgx ^ 16;
            uint32_t bh[4][2], bl[4][2];
#pragma unroll
            for (int ni = 0; ni < 4; ni++) {
                int rb = (wn * 32 + ni * 8 + gid) * 128 + tg * 4;
                bh[ni][0] = *(const uint32_t*)(Bh + rb + sgx);
                bh[ni][1] = *(const uint32_t*)(Bh + rb + sgy);
                bl[ni][0] = *(const uint32_t*)(Bl + rb + sgx);
                bl[ni][1] = *(const uint32_t*)(Bl + rb + sgy);
            }
#pragma unroll
            for (int mi = 0; mi < 4; mi++) {
                int rb0 = (wm * 64 + mi * 16 + gid) * 128 + tg * 4;
                int rb1 = rb0 + 1024;
                uint32_t ah[4], al[4];
                ah[0] = *(const uint32_t*)(Ah + rb0 + sgx);
                ah[1] = *(const uint32_t*)(Ah + rb1 + sgx);
                ah[2] = *(const uint32_t*)(Ah + rb0 + sgy);
                ah[3] = *(const uint32_t*)(Ah + rb1 + sgy);
                al[0] = *(const uint32_t*)(Al + rb0 + sgx);
                al[1] = *(const uint32_t*)(Al + rb1 + sgx);
                al[2] = *(const uint32_t*)(Al + rb0 + sgy);
                al[3] = *(const uint32_t*)(Al + rb1 + sgy);
#pragma unroll
                for (int ni = 0; ni < 4; ni++) {
                    mma_bf16(acc[mi][ni], ah, bh[ni]);
                    mma_bf16(acc[mi][ni], ah, bl[ni]);
                    mma_bf16(acc[mi][ni], al, bh[ni]);
                }
            }
        }
        if (nx) WSTS(buf ^ 1);
        __syncthreads();
        buf ^= 1;
    }

    // epilogue: bias + hi/lo bf16 out
#pragma unroll
    for (int mi = 0; mi < 4; mi++) {
        int lrow = wm * 64 + mi * 16 + gid;
#pragma unroll
        for (int ni = 0; ni < 4; ni++) {
            int colg = n0 + wn * 32 + ni * 8 + tg * 2;
            float b0 = bias[colg], b1 = bias[colg + 1];
            float2 v0 = make_float2(acc[mi][ni][0] + b0, acc[mi][ni][1] + b1);
            float2 v1 = make_float2(acc[mi][ni][2] + b0, acc[mi][ni][3] + b1);
            size_t o0 = (size_t)lrow       * 20480 + colg;
            size_t o1 = (size_t)(lrow + 8) * 20480 + colg;
            __nv_bfloat162 h0 = __float22bfloat162_rn(v0);
            __nv_bfloat162 h1 = __float22bfloat162_rn(v1);
            float2 f0 = __bfloat1622float2(h0), f1 = __bfloat1622float2(h1);
            *(__nv_bfloat162*)(OHi + o0) = h0;
            *(__nv_bfloat162*)(OHi + o1) = h1;
            *(__nv_bfloat162*)(OLo + o0) = __float22bfloat162_rn(make_float2(v0.x - f0.x, v0.y - f0.y));
            *(__nv_bfloat162*)(OLo + o1) = __float22bfloat162_rn(make_float2(v1.x - f1.x, v1.y - f1.y));
        }
    }
#undef AFILL
#undef WLDG
#undef WSTS
}

// ---------------- layer GEMM: merged D+T and A/B, split-bf16, cp.async --------
// blockIdx.x decode (64-row m-tiles):
//   bx < tilesD : merged D+T: out[r] = H[r]·Wblk0 + H[swap(r)]·Wblk40 (2x chunks)
//   else        : A/B: idx=bx-tilesD, l=idx/8+1, m0=(idx&7)*64
__global__ __launch_bounds__(256, 2)
void gemm_bf16(const __nv_bfloat16* __restrict__ Hhi, const __nv_bfloat16* __restrict__ Hlo,
               const __nv_bfloat16* __restrict__ Whi, const __nv_bfloat16* __restrict__ Wlo,
               float* __restrict__ OutD, float* __restrict__ OutA, float* __restrict__ OutB,
               int NOut, int K, int ldh, int ldw, int tilesD)
{
    extern __shared__ char dsm[];
    __shared__ int    s_hoff[64];
    __shared__ int    s_hoff2[64];
    __shared__ float* s_orow[64];
    __shared__ int    s_woff[128];
    __shared__ int    s_wok [128];

    const int tid  = threadIdx.x;
    const int lane = tid & 31;
    const int wid  = tid >> 5;
    const int gid  = lane >> 2;
    const int tg   = lane & 3;
    const int wm   = wid >> 2;
    const int wn   = wid & 3;
    const int n0   = blockIdx.y * 128;

    int bx = blockIdx.x;
    int mode, m0, l = 0, coloffW;
    if (bx < tilesD) { mode = 0; m0 = bx * 64; coloffW = 0; }
    else { mode = 2; int idx = bx - tilesD; l = (idx >> 3) + 1; m0 = (idx & 7) * 64; coloffW = l * K; }

    if (tid < 64) {
        int gr = m0 + tid;
        if (mode == 0) {
            int b = gr / 80, n = gr % 80;
            s_hoff[tid]  = gr * ldh;
            s_hoff2[tid] = (b * 80 + ((n + 40) % 80)) * ldh;
            s_orow[tid]  = OutD + (size_t)gr * NOut;
        } else {
            int part = gr >> 8; int bf = gr & 255; int mm = part ? l : (l - 1);
            int hrow = (bf >> 1) * 80 + (bf & 1) * 40 + mm;
            s_hoff[tid]  = hrow * ldh;
            s_hoff2[tid] = hrow * ldh;
            s_orow[tid]  = (part ? OutB : OutA) + (size_t)(bf * 40 + mm) * NOut;
        }
    }
    if (tid < 128) {
        int bn = n0 + tid;
        int valid = (bn < NOut);
        s_woff[tid] = valid ? (bn * ldw + coloffW) : 0;
        s_wok [tid] = valid ? 16 : 0;
    }
    __syncthreads();

    float acc[2][4][4];
#pragma unroll
    for (int mi = 0; mi < 2; mi++)
#pragma unroll
        for (int ni = 0; ni < 4; ni++)
#pragma unroll
            for (int q = 0; q < 4; q++) acc[mi][ni][q] = 0.f;

    const uint32_t dsm32 = smem_u32(dsm);
    const int nchH = K >> 6;
    const int nch  = (mode == 0) ? (nchH << 1) : nchH;
    const int w40  = 40 * K;

#define FILL(BUF, HT, AK, WK) do {                                             \
        uint32_t b32 = dsm32 + (BUF) * BUF_BYTES;                              \
        _Pragma("unroll")                                                      \
        for (int q = 0; q < 2; q++) {                                          \
            int s = q * 256 + tid;                                             \
            int row = s >> 3, sg = s & 7;                                      \
            uint32_t d = b32 + row * 128 + ((sg ^ (row & 7)) << 4);            \
            int ho = (HT)[row] + (AK) + sg * 8;                                \
            cpa16(d,          Hhi + ho, 16);                                   \
            cpa16(d + TILE_A, Hlo + ho, 16);                                   \
        }                                                                      \
        _Pragma("unroll")                                                      \
        for (int q = 0; q < 4; q++) {                                          \
            int s = q * 256 + tid;                                             \
            int row = s >> 3, sg = s & 7;                                      \
            uint32_t d = b32 + 2 * TILE_A + row * 128 + ((sg ^ (row & 7)) << 4); \
            int wo = s_woff[row] + (WK) + sg * 8;                              \
            int ok = s_wok[row];                                               \
            cpa16(d,          Whi + wo, ok);                                   \
            cpa16(d + TILE_B, Wlo + wo, ok);                                   \
        }                                                                      \
        cpa_commit();                                                          \
    } while (0)

    FILL(0, s_hoff, 0, 0);

    int buf = 0;
    for (int c = 0; c < nch; ++c) {
        const bool nx = (c + 1 < nch);
        if (nx) {
            int cn = c + 1;
            if (cn < nchH) { int a0 = cn * KCH; FILL(buf ^ 1, s_hoff, a0, a0); }
            else           { int a0 = (cn - nchH) * KCH; FILL(buf ^ 1, s_hoff2, a0, w40 + a0); }
        }
        if (nx) asm volatile("cp.async.wait_group 1;" ::: "memory");
        else    asm volatile("cp.async.wait_group 0;" ::: "memory");
        __syncthreads();

        const char* Ah = dsm + buf * BUF_BYTES;
        const char* Al = Ah + TILE_A;
        const char* Bh = Ah + 2 * TILE_A;
        const char* Bl = Bh + TILE_B;
#pragma unroll
        for (int k16 = 0; k16 < 4; k16++) {
            const int sgx = ((k16 * 2) ^ gid) << 4;
            const int sgy = sgx ^ 16;
            uint32_t bh[4][2], bl[4][2];
#pragma unroll
            for (int ni = 0; ni < 4; ni++) {
                int rb = (wn * 32 + ni * 8 + gid) * 128 + tg * 4;
                bh[ni][0] = *(const uint32_t*)(Bh + rb + sgx);
                bh[ni][1] = *(const uint32_t*)(Bh + rb + sgy);
                bl[ni][0] = *(const uint32_t*)(Bl + rb + sgx);
                bl[ni][1] = *(const uint32_t*)(Bl + rb + sgy);
            }
#pragma unroll
            for (int mi = 0; mi < 2; mi++) {
                int rb0 = (wm * 32 + mi * 16 + gid) * 128 + tg * 4;
                int rb1 = rb0 + 1024;
                uint32_t ah[4], al[4];
                ah[0] = *(const uint32_t*)(Ah + rb0 + sgx);
                ah[1] = *(const uint32_t*)(Ah + rb1 + sgx);
                ah[2] = *(const uint32_t*)(Ah + rb0 + sgy);
                ah[3] = *(const uint32_t*)(Ah + rb1 + sgy);
                al[0] = *(const uint32_t*)(Al + rb0 + sgx);
                al[1] = *(const uint32_t*)(Al + rb1 + sgx);
                al[2] = *(const uint32_t*)(Al + rb0 + sgy);
                al[3] = *(const uint32_t*)(Al + rb1 + sgy);
#pragma unroll
                for (int ni = 0; ni < 4; ni++) {
                    mma_bf16(acc[mi][ni], ah, bh[ni]);
                    mma_bf16(acc[mi][ni], ah, bl[ni]);
                    mma_bf16(acc[mi][ni], al, bh[ni]);
                }
            }
        }
        __syncthreads();
        buf ^= 1;
    }

    // epilogue: fp32
#pragma unroll
    for (int mi = 0; mi < 2; mi++) {
        int lrow = wm * 32 + mi * 16 + gid;
#pragma unroll
        for (int ni = 0; ni < 4; ni++) {
            int colg = n0 + wn * 32 + ni * 8 + tg * 2;
            if (colg < NOut) {
                float2 v0 = make_float2(acc[mi][ni][0], acc[mi][ni][1]);
                float2 v1 = make_float2(acc[mi][ni][2], acc[mi][ni][3]);
                *(float2*)(s_orow[lrow]     + colg) = v0;
                *(float2*)(s_orow[lrow + 8] + colg) = v1;
            }
        }
    }
#undef FILL
}

// ---------------- Combine: out = elu( bias + D(+T) + prefA(<j) + sufB(>j) ) ----
__global__ void combine2_kernel(const float* __restrict__ D,
                                const float* __restrict__ A, const float* __restrict__ B,
                                const float* __restrict__ bias, float* __restrict__ out,
                                __nv_bfloat16* __restrict__ OHi, __nv_bfloat16* __restrict__ OLo,
                                int Cout)
{
    __shared__ float As[40 * 64];
    __shared__ float Bs[40 * 64];
    const int bf = blockIdx.x;
    const int c0 = blockIdx.y * 64;
    const int tid = threadIdx.x;

    for (int t = tid; t < 40 * 64; t += 256) {
        int j = t >> 6, c = t & 63;
        size_t src = (size_t)(bf * 40 + j) * Cout + c0 + c;
        As[t] = A[src];
        Bs[t] = B[src];
    }
    __syncthreads();

    const int cc = tid & 63;
    const int jg = tid >> 6;
    const int j0 = jg * 10;

    float pref = 0.f, suf = 0.f;
    for (int m = 0; m < j0; m++)      pref += As[m * 64 + cc];
    for (int m = j0 + 1; m < 40; m++) suf  += Bs[m * 64 + cc];

    const int b = bf >> 1, f = bf & 1;
    const float bias_c = bias[c0 + cc];
    const size_t rbase = (size_t)(b * 80 + f * 40) * Cout + c0 + cc;
#pragma unroll
    for (int j = j0; j < j0 + 10; j++) {
        size_t r = rbase + (size_t)j * Cout;
        float v = bias_c + D[r] + pref + suf;
        v = (v > 0.f) ? v : expm1f(v);
        if (out) out[r] = v;
        if (OHi) {
            __nv_bfloat16 h = __float2bfloat16(v);
            OHi[r] = h;
            OLo[r] = __float2bfloat16(v - __bfloat162float(h));
        }
        if (j < 39) {
            pref += As[j * 64 + cc];
            suf  -= Bs[(j + 1) * 64 + cc];
        }
    }
}

// ---------------- Layer 4 direct: Cout=2, Cin=64, spiral evaluated in-kernel ----
__global__ __launch_bounds__(256)
void spiral_small_kernel(const float* __restrict__ Hin, const float* __restrict__ W4,
                         const float* __restrict__ b4, float* __restrict__ out)
{
    __shared__ float hs[80 * 64];
    __shared__ float ws[2 * 41 * 64];
    const int b = blockIdx.x;
    const int tid = threadIdx.x;
    const int wid = tid >> 5;
    const int lane = tid & 31;

    const float* hsrc = Hin + (size_t)b * 80 * 64;
    for (int t = tid; t < 80 * 64; t += 256) hs[t] = hsrc[t];
    for (int t = tid; t < 2 * 41 * 64; t += 256) ws[t] = W4[t];
    __syncthreads();

    for (int j = wid; j < 80; j += 8) {
        const int f  = (j >= 40) ? 40 : 0;
        const int jj = j - f;
        const int tnode = (j < 40) ? j + 40 : j - 40;
#pragma unroll
        for (int c = 0; c < 2; c++) {
            const float* w = ws + c * (41 * 64);
            float sum = 0.f;
            for (int idx = lane; idx < 41 * 64; idx += 32) {
                int p = idx >> 6, k = idx & 63;
                int node;
                if (p == 0)       node = j;
                else if (p <= 39) node = f + ((p - 1 < jj) ? p - 1 : p);
                else              node = tnode;
                sum += w[idx] * hs[node * 64 + k];
            }
#pragma unroll
            for (int o = 16; o > 0; o >>= 1)
                sum += __shfl_xor_sync(0xFFFFFFFFu, sum, o);
            if (lane == 0)
                out[(size_t)(b * 80 + j) * 2 + c] = sum + b4[c];
        }
    }
}

// ---------------- Host-side driver ----------------
extern "C" void kernel_launch(void* const* d_in, const int* in_sizes, int n_in,
                              void* d_out, int out_size)
{
    const float* x  = (const float*)d_in[0];
    const float* W0 = (const float*)d_in[1];
    const float* b0 = (const float*)d_in[2];
    const float* W1 = (const float*)d_in[3];
    const float* b1 = (const float*)d_in[4];
    const float* W2 = (const float*)d_in[5];
    const float* b2 = (const float*)d_in[6];
    const float* W3 = (const float*)d_in[7];
    const float* b3 = (const float*)d_in[8];
    const float* W4 = (const float*)d_in[9];
    const float* b4 = (const float*)d_in[10];
    float* out = (float*)d_out;

    float *dD, *dA, *dB, *h2;
    __nv_bfloat16 *whi, *wlo, *xhi, *xlo, *hahi, *halo, *hbhi, *hblo;
    cudaGetSymbolAddress((void**)&dD, g_D);
    cudaGetSymbolAddress((void**)&dA, g_A);
    cudaGetSymbolAddress((void**)&dB, g_Bf);
    cudaGetSymbolAddress((void**)&h2, g_h2);
    cudaGetSymbolAddress((void**)&whi, g_whi);
    cudaGetSymbolAddress((void**)&wlo, g_wlo);
    cudaGetSymbolAddress((void**)&xhi, g_xhi);
    cudaGetSymbolAddress((void**)&xlo, g_xlo);
    cudaGetSymbolAddress((void**)&hahi, g_hahi);
    cudaGetSymbolAddress((void**)&halo, g_halo);
    cudaGetSymbolAddress((void**)&hbhi, g_hbhi);
    cudaGetSymbolAddress((void**)&hblo, g_hblo);

    cudaFuncSetAttribute(gemm_bf16, cudaFuncAttributeMaxDynamicSharedMemorySize, GEMM_SMEM);
    cudaFuncSetAttribute(gemm0_kernel, cudaFuncAttributeMaxDynamicSharedMemorySize, G0_SMEM);

    // Split x + W1..W3 to bf16 hi/lo (W0 handled in gemm0 directly)
    conv_all<<<(CXT + 255) / 256, 256>>>((const float4*)x, (const float4*)W1,
                                         (const float4*)W2, (const float4*)W3);

    // gemm0: h1(bf16 hi/lo) = x @ W0^T + b0  (fp32 W streamed, converted in-kernel)
    gemm0_kernel<<<dim3(1, 160), 256, G0_SMEM>>>(xhi, xlo, W0, b0, hahi, halo);

    const int tilesD = NB * NN / 64;             // 160
    const int gx = tilesD + 39 * 8;              // 472 (merged D+T)

    // Layer 1: 256->256, ELU  (in: ha, out: hb)
    gemm_bf16<<<dim3(gx, 2), 256, GEMM_SMEM>>>(
        hahi, halo, whi + W1OFF, wlo + W1OFF,
        dD, dA, dB, 256, 256, 256, 10496, tilesD);
    combine2_kernel<<<dim3(NB * 2, 4), 256>>>(dD, dA, dB, b1,
        (float*)0, hbhi, hblo, 256);

    // Layer 2: 256->128, ELU  (in: hb, out: ha)
    gemm_bf16<<<dim3(gx, 1), 256, GEMM_SMEM>>>(
        hbhi, hblo, whi + W2OFF, wlo + W2OFF,
        dD, dA, dB, 128, 256, 256, 10496, tilesD);
    combine2_kernel<<<dim3(NB * 2, 2), 256>>>(dD, dA, dB, b2,
        (float*)0, hahi, halo, 128);

    // Layer 3: 128->64, ELU  (in: ha, out: h2 fp32 for spiral)
    gemm_bf16<<<dim3(gx, 1), 256, GEMM_SMEM>>>(
        hahi, halo, whi + W3OFF, wlo + W3OFF,
        dD, dA, dB, 64, 128, 128, 5248, tilesD);
    combine2_kernel<<<dim3(NB * 2, 1), 256>>>(dD, dA, dB, b3,
        h2, (__nv_bfloat16*)0, (__nv_bfloat16*)0, 64);

    // Layer 4 (64 -> 2, no ELU): direct spiral evaluation
    spiral_small_kernel<<<NB, 256>>>(h2, W4, b4, out);
}